// round 1
// baseline (speedup 1.0000x reference)
#include <cuda_runtime.h>
#include <cstdint>

// MXFP (EXP_W=2, MAN_W=1, GROUP=32) quantize-dequantize, fp32 -> fp32.
// Representable magnitudes: 0, {0.5,0.75,1,1.5,2,3,4,6} * scale, scale = 2^(floor(log2 max|g|)-2).

__device__ __forceinline__ float pow2i(int k) {
    // exact 2^k for k in [-126,127]
    return __uint_as_float((uint32_t)(k + 127) << 23);
}

__device__ __forceinline__ float quant1(float v, float inv, float scale) {
    float a = fabsf(v) * inv;            // exact (power-of-two multiply), a < 8
    float q = 0.0f;
    if (a > 0.25f) {                     // a <= lim_zero (=0.25) -> 0
        int e = (int)(__float_as_uint(a) >> 23) - 127;   // floor(log2 a), a normal here
        // mantissa round to 1 bit: round-half-even on a*2^(1-e) in [2,4)
        float r = rintf(a * pow2i(1 - e)) * pow2i(e - 1);
        q = fminf(fmaxf(r, 0.5f), 6.0f); // clip to [min_repr, max_repr]
    }
    return copysignf(q * scale, v);
}

__global__ void __launch_bounds__(256)
mxfp_quant_kernel(const float4* __restrict__ x, float4* __restrict__ y, int n4) {
    int i = blockIdx.x * blockDim.x + threadIdx.x;
    if (i >= n4) return;

    float4 v = x[i];

    // per-thread max of 4, then reduce over the 8-lane octet (one 32-elem group)
    float m = fmaxf(fmaxf(fabsf(v.x), fabsf(v.y)), fmaxf(fabsf(v.z), fabsf(v.w)));
    m = fmaxf(m, __shfl_xor_sync(0xffffffffu, m, 1));
    m = fmaxf(m, __shfl_xor_sync(0xffffffffu, m, 2));
    m = fmaxf(m, __shfl_xor_sync(0xffffffffu, m, 4));
    if (m == 0.0f) m = 1.0f;

    // pot = floor(log2(m)) - 2, clipped to [-127, 128]
    int E;
    frexpf(m, &E);                 // m = f*2^E, f in [0.5,1)  => floor(log2 m) = E-1
    int pot = E - 3;
    pot = max(-127, min(128, pot));
    float scale = ldexpf(1.0f, pot);    // exact, handles subnormal 2^-127
    float inv   = ldexpf(1.0f, -pot);

    float4 o;
    o.x = quant1(v.x, inv, scale);
    o.y = quant1(v.y, inv, scale);
    o.z = quant1(v.z, inv, scale);
    o.w = quant1(v.w, inv, scale);
    y[i] = o;
}

extern "C" void kernel_launch(void* const* d_in, const int* in_sizes, int n_in,
                              void* d_out, int out_size) {
    const float4* x = (const float4*)d_in[0];
    float4* y = (float4*)d_out;
    int n = in_sizes[0];
    int n4 = n >> 2;                      // n is 4*32*2048*128, divisible by 4
    int threads = 256;
    int blocks = (n4 + threads - 1) / threads;
    mxfp_quant_kernel<<<blocks, threads>>>(x, y, n4);
}

// round 2
// speedup vs baseline: 1.0882x; 1.0882x over previous
#include <cuda_runtime.h>
#include <cstdint>

// MXFP (EXP_W=2, MAN_W=1, GROUP=32) quantize-dequantize, fp32 -> fp32.
// Grid magnitudes: 0, {0.5,0.75,1,1.5,2,3,4,6} * scale, scale = 2^(floor(log2 max|g|)-2).

__device__ __forceinline__ float pow2i(int k) {
    // exact 2^k for k in [-126,127] (normal range)
    return __uint_as_float((uint32_t)(k + 127) << 23);
}

// Round |v|*inv to the E2M1 grid and rescale. a in [0,8).
__device__ __forceinline__ float q_elem(float v, float inv, float scale) {
    float a = __fmul_rn(fabsf(v), inv);          // exact: inv is power of two
    // RNE to 1 mantissa bit: c = a*2^22 (exact); (a+c)-c snaps a to grid 2^(e-1)
    float c = __fmul_rn(a, 4194304.0f);
    float r = __fsub_rn(__fadd_rn(a, c), c);
    r = fminf(fmaxf(r, 0.5f), 6.0f);             // clip to [min_repr, max_repr]
    r = (a > 0.25f) ? r : 0.0f;                  // |x|/scale <= lim_zero -> 0
    return copysignf(__fmul_rn(r, scale), v);    // scale mul exact (pow2)
}

// Per-group (32 elems = 8 lanes x float4) scale from the group max m (>0).
__device__ __forceinline__ void make_scales(float m, float& inv, float& scale) {
    // floor(log2 m) == biased_exp - 127 for normal m; for subnormal m the
    // value (-129-2) under-shoots and clips to -127 exactly like the reference.
    int pot = (int)(__float_as_uint(m) >> 23) - 129;   // floor(log2 m) - 2
    pot = max(pot, -127);                              // upper bound <=125 naturally
    inv = pow2i(-pot);                                 // -pot in [-125,127]
    scale = (pot >= -126) ? pow2i(pot)
                          : __uint_as_float(0x00400000u);  // 2^-127 subnormal
}

__global__ void __launch_bounds__(256)
mxfp_quant_kernel(const float4* __restrict__ x, float4* __restrict__ y) {
    int base = blockIdx.x * 512 + threadIdx.x;   // two tiles of 256 float4s
    int i1 = base + 256;

    float4 v0 = x[base];
    float4 v1 = x[i1];

    // per-thread max of 4, two independent chains
    float m0 = fmaxf(fmaxf(fabsf(v0.x), fabsf(v0.y)), fmaxf(fabsf(v0.z), fabsf(v0.w)));
    float m1 = fmaxf(fmaxf(fabsf(v1.x), fabsf(v1.y)), fmaxf(fabsf(v1.z), fabsf(v1.w)));

    // 8-lane octet reduction = one 32-elem group per load slot
    m0 = fmaxf(m0, __shfl_xor_sync(0xffffffffu, m0, 1));
    m1 = fmaxf(m1, __shfl_xor_sync(0xffffffffu, m1, 1));
    m0 = fmaxf(m0, __shfl_xor_sync(0xffffffffu, m0, 2));
    m1 = fmaxf(m1, __shfl_xor_sync(0xffffffffu, m1, 2));
    m0 = fmaxf(m0, __shfl_xor_sync(0xffffffffu, m0, 4));
    m1 = fmaxf(m1, __shfl_xor_sync(0xffffffffu, m1, 4));
    if (m0 == 0.0f) m0 = 1.0f;
    if (m1 == 0.0f) m1 = 1.0f;

    float inv0, sc0, inv1, sc1;
    make_scales(m0, inv0, sc0);
    make_scales(m1, inv1, sc1);

    float4 o0, o1;
    o0.x = q_elem(v0.x, inv0, sc0);
    o0.y = q_elem(v0.y, inv0, sc0);
    o0.z = q_elem(v0.z, inv0, sc0);
    o0.w = q_elem(v0.w, inv0, sc0);
    o1.x = q_elem(v1.x, inv1, sc1);
    o1.y = q_elem(v1.y, inv1, sc1);
    o1.z = q_elem(v1.z, inv1, sc1);
    o1.w = q_elem(v1.w, inv1, sc1);

    y[base] = o0;
    y[i1]   = o1;
}

extern "C" void kernel_launch(void* const* d_in, const int* in_sizes, int n_in,
                              void* d_out, int out_size) {
    const float4* x = (const float4*)d_in[0];
    float4* y = (float4*)d_out;
    int n = in_sizes[0];                 // 33,554,432 = 16384 * 512 * 4
    int n4 = n >> 2;
    int blocks = n4 / 512;               // exact for this shape
    mxfp_quant_kernel<<<blocks, 256>>>(x, y);
}